// round 5
// baseline (speedup 1.0000x reference)
#include <cuda_runtime.h>
#include <cuda_bf16.h>
#include <cstdint>
#include <math.h>

typedef unsigned int u32;

#define VV    32768
#define NSEQ  1024
#define LSEQ  32
#define CD    128
#define DIc   256

typedef __nv_bfloat16 bf16;

// ---------------- scratch (device globals: allocation-free) ----------------
__device__ __align__(16) bf16  g_xn  [(size_t)VV * CD];       // normalized x, [vox][C]
__device__ __align__(16) bf16  g_z   [3ull * VV * DIc];       // silu(z),     [r][n][t][256]
__device__ __align__(16) bf16  g_xc  [3ull * VV * DIc];       // conv+silu,   [r][n][t][256]
__device__ __align__(16) float g_dbl [3ull * VV * 40];        // x_proj out,  [r][n][t][40]
__device__ __align__(16) bf16  g_ymid[3ull * VV * DIc];       // scan out,    [r][n][t][256]
__device__ __align__(16) bf16  g_yb  [(size_t)VV * 384];      // cat [vox][3*128]
__device__ __align__(16) bf16  g_f   [(size_t)VV * CD];       // gelu(fusion) [vox][128]

// bf16 weights
__device__ __align__(16) bf16 g_w_in [3 * 512 * 128];
__device__ __align__(16) bf16 g_w_xp [3 * 40 * 256];
__device__ __align__(16) bf16 g_w_out[3 * 128 * 256];
__device__ __align__(16) bf16 g_w_f  [128 * 384];
__device__ __align__(16) bf16 g_w_p  [128 * 128];

// branch (r) sequence (n,t) -> voxel index (d*1024 + h*32 + w)
__device__ __forceinline__ int vox_of(int r, int m) {
    int n = m >> 5, t = m & 31;
    if (r == 0) return (t << 10) + n;                              // axial
    if (r == 1) return ((n >> 5) << 10) + (t << 5) + (n & 31);     // coronal
    return (n << 5) + t;                                           // sagittal
}

// ---------------- weight convert fp32 -> bf16 ----------------
__global__ __launch_bounds__(256) void cvt_kernel(
    const float* __restrict__ in_w, const float* __restrict__ xp_w,
    const float* __restrict__ out_w, const float* __restrict__ fw,
    const float* __restrict__ pw)
{
    const int i = blockIdx.x * 256 + threadIdx.x;
    if (i < 3 * 512 * 128) g_w_in[i]  = __float2bfloat16(in_w[i]);
    if (i < 3 * 40 * 256)  g_w_xp[i]  = __float2bfloat16(xp_w[i]);
    if (i < 3 * 128 * 256) g_w_out[i] = __float2bfloat16(out_w[i]);
    if (i < 128 * 384)     g_w_f[i]   = __float2bfloat16(fw[i]);
    if (i < 128 * 128)     g_w_p[i]   = __float2bfloat16(pw[i]);
}

// ---------------- LayerNorm over channels, write bf16 [vox][C] ----------------
__global__ __launch_bounds__(256) void ln_kernel(
    const float* __restrict__ x, const float* __restrict__ g, const float* __restrict__ b)
{
    __shared__ float sm[128][33];
    __shared__ float smu[32], srs[32];
    const int v0 = blockIdx.x * 32;
    const int tid = threadIdx.x;

    #pragma unroll
    for (int it = 0; it < 16; it++) {
        int e = it * 256 + tid;
        int c = e >> 5, vi = e & 31;
        sm[c][vi] = x[(size_t)c * VV + v0 + vi];
    }
    __syncthreads();
    if (tid < 32) {
        float s = 0.f, s2 = 0.f;
        #pragma unroll 8
        for (int c = 0; c < 128; c++) { float v = sm[c][tid]; s += v; s2 += v * v; }
        float m = s * (1.f / 128.f);
        float var = s2 * (1.f / 128.f) - m * m;
        smu[tid] = m;
        srs[tid] = rsqrtf(var + 1e-5f);
    }
    __syncthreads();
    #pragma unroll
    for (int it = 0; it < 16; it++) {
        int e = it * 256 + tid;
        int c = e & 127, vi = e >> 7;
        float v = (sm[c][vi] - smu[vi]) * srs[vi] * g[c] + b[c];
        g_xn[(size_t)(v0 + vi) * 128 + c] = __float2bfloat16(v);
    }
}

// ---------------- tensor-core / async-copy helpers ----------------
__device__ __forceinline__ void ldsm4(u32* r, const void* p) {
    u32 addr = (u32)__cvta_generic_to_shared(p);
    asm volatile("ldmatrix.sync.aligned.m8n8.x4.shared.b16 {%0,%1,%2,%3}, [%4];"
        : "=r"(r[0]), "=r"(r[1]), "=r"(r[2]), "=r"(r[3]) : "r"(addr));
}
__device__ __forceinline__ void mma16816(float* c, const u32* a, u32 b0, u32 b1) {
    asm volatile("mma.sync.aligned.m16n8k16.row.col.f32.bf16.bf16.f32 "
        "{%0,%1,%2,%3}, {%4,%5,%6,%7}, {%8,%9}, {%0,%1,%2,%3};"
        : "+f"(c[0]), "+f"(c[1]), "+f"(c[2]), "+f"(c[3])
        : "r"(a[0]), "r"(a[1]), "r"(a[2]), "r"(a[3]), "r"(b0), "r"(b1));
}
__device__ __forceinline__ void cpa16(void* dst, const void* src, bool pred) {
    u32 d = (u32)__cvta_generic_to_shared(dst);
    int sz = pred ? 16 : 0;
    asm volatile("cp.async.ca.shared.global [%0], [%1], 16, %2;" :: "r"(d), "l"(src), "r"(sz));
}
__device__ __forceinline__ void cpa_commit() { asm volatile("cp.async.commit_group;"); }
template <int N> __device__ __forceinline__ void cpa_wait() {
    asm volatile("cp.async.wait_group %0;" :: "n"(N));
}
__device__ __forceinline__ float siluf(float s) { return s / (1.f + __expf(-s)); }

// ============ A-resident N-loop GEMM (MODEs 1,2,3) ============
// Block: 128 M-rows, full K in smem; loops over all N in 64-wide j-chunks,
// B (weights, L2-resident) streamed through a cp.async double buffer.
// MODE 1: in_proj  A=g_xn gathered (K=128), N=512 -> conv+silu -> g_xc / silu -> g_z
// MODE 2: out_proj A=g_ymid[r]    (K=256), N=128 -> scatter g_yb
// MODE 3: fusion   A=g_yb         (K=384), N=128 -> +bias, gelu -> g_f
template <int MODE>
__global__ __launch_bounds__(256) void bgemm_nl_kernel(
    const float* __restrict__ bias,
    const float* __restrict__ conv_w, const float* __restrict__ conv_b)
{
    constexpr int Kc  = (MODE == 1) ? 128 : (MODE == 2) ? 256 : 384;
    constexpr int NJ  = (MODE == 1) ? 8 : 2;
    constexpr int KP  = Kc + 8;          // padded row stride (odd # of 16B chunks)
    constexpr int KST = Kc / 32;
    constexpr int TOT = NJ * KST;

    extern __shared__ __align__(16) char dyn[];
    bf16* As = (bf16*)dyn;                                // [128][KP]
    bf16* Bs = (bf16*)(dyn + (size_t)128 * KP * 2);       // [2][64][40]
    bf16* Cs = (bf16*)(dyn + (size_t)128 * KP * 2 + 10240); // [128][72] (MODE 1)

    const int r   = blockIdx.y;
    const int m0  = blockIdx.x * 128;
    const int tid = threadIdx.x;
    const int lane = tid & 31, warp = tid >> 5;
    const int wm = (warp & 3) * 32, wn = (warp >> 2) * 32;
    const int lrow = tid >> 2;         // 0..63
    const int lk8  = (tid & 3) << 3;   // 0,8,16,24
    const int srow = lane & 15;
    const int scol = (lane >> 4) << 3;

    const bf16* Bbase;
    if (MODE == 1)      Bbase = g_w_in  + (size_t)r * 512 * 128;
    else if (MODE == 2) Bbase = g_w_out + (size_t)r * 128 * 256;
    else                Bbase = g_w_f;

    // ---- load full A tile (once) ----
    for (int idx = tid; idx < 128 * (Kc / 8); idx += 256) {
        const int row = idx / (Kc / 8);
        const int c8  = (idx % (Kc / 8)) * 8;
        const bf16* src;
        if (MODE == 1)      src = g_xn   + (size_t)vox_of(r, m0 + row) * 128 + c8;
        else if (MODE == 2) src = g_ymid + (size_t)r * VV * 256 + (size_t)(m0 + row) * 256 + c8;
        else                src = g_yb   + (size_t)(m0 + row) * 384 + c8;
        cpa16(&As[row * KP + c8], src, true);
    }
    // ---- B stage 0 ----
    cpa16(&Bs[lrow * 40 + lk8], Bbase + (size_t)lrow * Kc + lk8, true);
    cpa_commit();

    float acc[2][4][4];
    int sb = 0;
    const int grp = lane >> 2, tg = lane & 3;

    for (int s = 0; s < TOT; s++) {
        const int jc = s / KST, st = s % KST;
        if (st == 0) {
            #pragma unroll
            for (int f = 0; f < 2; f++)
                #pragma unroll
                for (int n = 0; n < 4; n++)
                    #pragma unroll
                    for (int i = 0; i < 4; i++) acc[f][n][i] = 0.f;
        }
        const int sn = s + 1;
        if (sn < TOT) {
            const int jn = sn / KST, stn = sn % KST;
            cpa16(&Bs[(sb ^ 1) * 2560 + lrow * 40 + lk8],
                  Bbase + (size_t)(jn * 64 + lrow) * Kc + stn * 32 + lk8, true);
        }
        cpa_commit();
        cpa_wait<1>();
        __syncthreads();
        #pragma unroll
        for (int kk = 0; kk < 32; kk += 16) {
            const int ak = st * 32 + kk;
            u32 a[2][4], b[2][4];
            ldsm4(a[0], &As[(wm +      srow) * KP + ak + scol]);
            ldsm4(a[1], &As[(wm + 16 + srow) * KP + ak + scol]);
            ldsm4(b[0], &Bs[sb * 2560 + (wn +      srow) * 40 + kk + scol]);
            ldsm4(b[1], &Bs[sb * 2560 + (wn + 16 + srow) * 40 + kk + scol]);
            #pragma unroll
            for (int f = 0; f < 2; f++)
                #pragma unroll
                for (int n = 0; n < 4; n++)
                    mma16816(acc[f][n], a[f], b[n >> 1][n & 1], b[n >> 1][(n & 1) + 2]);
        }
        __syncthreads();
        sb ^= 1;

        if (st != KST - 1) continue;

        // ---- per-j-chunk epilogue ----
        const int j0 = jc * 64;
        if (MODE == 1) {
            if (j0 < 256) {
                // xp half: stage -> causal conv + silu -> g_xc
                #pragma unroll
                for (int f = 0; f < 2; f++)
                    #pragma unroll
                    for (int half = 0; half < 2; half++) {
                        const int mm = wm + f * 16 + grp + half * 8;
                        #pragma unroll
                        for (int n = 0; n < 4; n++) {
                            const int jj = wn + n * 8 + tg * 2;
                            Cs[mm * 72 + jj]     = __float2bfloat16(acc[f][n][half * 2 + 0]);
                            Cs[mm * 72 + jj + 1] = __float2bfloat16(acc[f][n][half * 2 + 1]);
                        }
                    }
                __syncthreads();
                const int c = tid & 63, sq = tid >> 6;
                const int gdi = j0 + c;
                const int wb = (r * 256 + gdi) * 4;
                const float w0 = conv_w[wb], w1 = conv_w[wb + 1], w2 = conv_w[wb + 2], w3 = conv_w[wb + 3];
                const float cb = conv_b[r * 256 + gdi];
                float x0 = 0.f, x1 = 0.f, x2 = 0.f;
                bf16* dst = g_xc + ((size_t)r * VV + m0 + sq * 32) * 256 + gdi;
                #pragma unroll
                for (int t = 0; t < 32; t++) {
                    const float xv = __bfloat162float(Cs[(sq * 32 + t) * 72 + c]);
                    const float ss = x0 * w0 + x1 * w1 + x2 * w2 + xv * w3 + cb;
                    dst[(size_t)t * 256] = __float2bfloat16(siluf(ss));
                    x0 = x1; x1 = x2; x2 = xv;
                }
                __syncthreads();
            } else {
                // z half -> silu -> g_z
                #pragma unroll
                for (int f = 0; f < 2; f++)
                    #pragma unroll
                    for (int half = 0; half < 2; half++) {
                        const int m = m0 + wm + f * 16 + grp + half * 8;
                        #pragma unroll
                        for (int n = 0; n < 4; n++) {
                            const int j = j0 - 256 + wn + n * 8 + tg * 2;
                            __nv_bfloat162 v;
                            v.x = __float2bfloat16(siluf(acc[f][n][half * 2 + 0]));
                            v.y = __float2bfloat16(siluf(acc[f][n][half * 2 + 1]));
                            *(__nv_bfloat162*)&g_z[((size_t)r * VV + m) * 256 + j] = v;
                        }
                    }
            }
        } else if (MODE == 2) {
            #pragma unroll
            for (int f = 0; f < 2; f++)
                #pragma unroll
                for (int half = 0; half < 2; half++) {
                    const int m = m0 + wm + f * 16 + grp + half * 8;
                    const int vox = vox_of(r, m);
                    #pragma unroll
                    for (int n = 0; n < 4; n++) {
                        const int j = j0 + wn + n * 8 + tg * 2;
                        __nv_bfloat162 v;
                        v.x = __float2bfloat16(acc[f][n][half * 2 + 0]);
                        v.y = __float2bfloat16(acc[f][n][half * 2 + 1]);
                        *(__nv_bfloat162*)&g_yb[(size_t)vox * 384 + r * 128 + j] = v;
                    }
                }
        } else {
            #pragma unroll
            for (int f = 0; f < 2; f++)
                #pragma unroll
                for (int half = 0; half < 2; half++) {
                    const int m = m0 + wm + f * 16 + grp + half * 8;
                    #pragma unroll
                    for (int n = 0; n < 4; n++) {
                        const int j = j0 + wn + n * 8 + tg * 2;
                        float u0 = acc[f][n][half * 2 + 0] + bias[j];
                        float u1 = acc[f][n][half * 2 + 1] + bias[j + 1];
                        float gl0 = 0.5f * u0 * (1.f + erff(u0 * 0.70710678118654752f));
                        float gl1 = 0.5f * u1 * (1.f + erff(u1 * 0.70710678118654752f));
                        __nv_bfloat162 v; v.x = __float2bfloat16(gl0); v.y = __float2bfloat16(gl1);
                        *(__nv_bfloat162*)&g_f[(size_t)m * 128 + j] = v;
                    }
                }
        }
    }
}

// ============ streaming GEMMs (MODEs 0,4), K-staged double buffer ============
// MODE 0: x_proj  A=g_xc[r], B=g_w_xp[r](40x256) -> g_dbl (fp32)
// MODE 4: proj    A=g_w_p,   B=g_f (N=VV), +bias +residual -> out (fp32)
template <int MODE>
__global__ __launch_bounds__(256) void bgemm_kernel(
    const float* __restrict__ bias, const float* __restrict__ resid, float* __restrict__ outp)
{
    constexpr int Kc = (MODE == 4) ? 128 : 256;
    constexpr int Nc = (MODE == 0) ? 40 : VV;
    constexpr int NSTAGE = Kc / 32;

    __shared__ __align__(16) bf16 As[2][128][40];
    __shared__ __align__(16) bf16 Bs[2][64][40];

    const int r   = blockIdx.z;
    const int m0  = blockIdx.y * 128;
    const int j0  = blockIdx.x * 64;
    const int tid = threadIdx.x;
    const int lane = tid & 31, warp = tid >> 5;
    const int wm = (warp & 3) * 32, wn = (warp >> 2) * 32;

    const bf16* Abase = (MODE == 0) ? (g_xc + (size_t)r * VV * 256) : g_w_p;
    const bf16* Bbase = (MODE == 0) ? (g_w_xp + (size_t)r * 40 * 256) : g_f;

    const int lrow = tid >> 2;
    const int lk8  = (tid & 3) << 3;

    const bf16* arow0 = Abase + (size_t)(m0 + lrow) * Kc;
    const bf16* arow1 = Abase + (size_t)(m0 + lrow + 64) * Kc;
    const int bj = j0 + lrow;
    const bf16* brow = Bbase + (size_t)bj * Kc;
    const bool bvalid = (Nc % 64 == 0) || (bj < Nc);

    float acc[2][4][4];
    #pragma unroll
    for (int f = 0; f < 2; f++)
        #pragma unroll
        for (int n = 0; n < 4; n++)
            #pragma unroll
            for (int i = 0; i < 4; i++) acc[f][n][i] = 0.f;

    const int srow = lane & 15;
    const int scol = (lane >> 4) << 3;

    cpa16(&As[0][lrow     ][lk8], arow0 + lk8, true);
    cpa16(&As[0][lrow + 64][lk8], arow1 + lk8, true);
    cpa16(&Bs[0][lrow     ][lk8], brow  + lk8, bvalid);
    cpa_commit();

    int sb = 0;
    #pragma unroll
    for (int st = 0; st < NSTAGE; st++) {
        const int kn = (st + 1) * 32;
        if (kn < Kc) {
            cpa16(&As[sb ^ 1][lrow     ][lk8], arow0 + kn + lk8, true);
            cpa16(&As[sb ^ 1][lrow + 64][lk8], arow1 + kn + lk8, true);
            cpa16(&Bs[sb ^ 1][lrow     ][lk8], brow  + kn + lk8, bvalid);
        }
        cpa_commit();
        cpa_wait<1>();
        __syncthreads();
        #pragma unroll
        for (int kk = 0; kk < 32; kk += 16) {
            u32 a[2][4], b[2][4];
            ldsm4(a[0], &As[sb][wm +      srow][kk + scol]);
            ldsm4(a[1], &As[sb][wm + 16 + srow][kk + scol]);
            ldsm4(b[0], &Bs[sb][wn +      srow][kk + scol]);
            ldsm4(b[1], &Bs[sb][wn + 16 + srow][kk + scol]);
            #pragma unroll
            for (int f = 0; f < 2; f++)
                #pragma unroll
                for (int n = 0; n < 4; n++)
                    mma16816(acc[f][n], a[f], b[n >> 1][n & 1], b[n >> 1][(n & 1) + 2]);
        }
        __syncthreads();
        sb ^= 1;
    }

    const int grp = lane >> 2, tg = lane & 3;
    #pragma unroll
    for (int f = 0; f < 2; f++) {
        #pragma unroll
        for (int half = 0; half < 2; half++) {
            const int m = m0 + wm + f * 16 + grp + half * 8;
            #pragma unroll
            for (int n = 0; n < 4; n++) {
                const int j = j0 + wn + n * 8 + tg * 2;
                const float c0 = acc[f][n][half * 2 + 0];
                const float c1 = acc[f][n][half * 2 + 1];
                if (MODE == 0) {
                    if (j < 40)
                        *(float2*)&g_dbl[(size_t)r * VV * 40 + (size_t)m * 40 + j] = make_float2(c0, c1);
                } else {
                    float2 rd = *(const float2*)&resid[(size_t)m * VV + j];
                    *(float2*)&outp[(size_t)m * VV + j] =
                        make_float2(c0 + bias[m] + rd.x, c1 + bias[m] + rd.y);
                }
            }
        }
    }
}

// ---------------- dt + selective scan + gate, fused ----------------
__global__ __launch_bounds__(256) void scan_kernel(
    const float* __restrict__ dt_w, const float* __restrict__ dt_b,
    const float* __restrict__ A_log, const float* __restrict__ Dparam)
{
    __shared__ float sm[LSEQ * 40];
    const int r = blockIdx.y, n = blockIdx.x, di = threadIdx.x;

    const float* dblp = g_dbl + (size_t)(r * NSEQ + n) * LSEQ * 40;
    for (int e = di; e < LSEQ * 40; e += 256) sm[e] = dblp[e];
    __syncthreads();

    float dtw[8];
    #pragma unroll
    for (int k = 0; k < 8; k++) dtw[k] = dt_w[(r * 256 + di) * 8 + k];
    const float dtb = dt_b[r * 256 + di];
    const float Dpv = Dparam[r * 256 + di];

    float Av[16];
    #pragma unroll
    for (int s = 0; s < 16; s++) Av[s] = -__expf(A_log[(r * 256 + di) * 16 + s]);
    bool ap = true;
    #pragma unroll
    for (int s = 1; s < 16; s++)
        ap = ap && (fabsf(Av[s] - (float)(s + 1) * Av[0]) <= 1e-4f * fabsf(Av[s]) + 1e-6f);

    float h[16];
    #pragma unroll
    for (int s = 0; s < 16; s++) h[s] = 0.f;

    const bf16* xcp = g_xc   + ((size_t)(r * NSEQ + n) * LSEQ) * 256 + di;
    const bf16* zp  = g_z    + ((size_t)(r * NSEQ + n) * LSEQ) * 256 + di;
    bf16*       yp  = g_ymid + ((size_t)(r * NSEQ + n) * LSEQ) * 256 + di;

    for (int t = 0; t < LSEQ; t++) {
        const float* row = sm + t * 40;
        float xl = dtb;
        #pragma unroll
        for (int k = 0; k < 8; k++) xl += row[k] * dtw[k];
        const float dt = (xl > 15.f) ? xl : log1pf(__expf(xl));

        const float xcv = __bfloat162float(xcp[(size_t)t * 256]);
        const float sz  = __bfloat162float(zp [(size_t)t * 256]);   // pre-silu'ed
        const float du  = dt * xcv;
        float y = 0.f;

        if (ap) {
            const float p = __expf(dt * Av[0]);
            float dAk = p;
            #pragma unroll
            for (int s = 0; s < 16; s++) {
                h[s] = dAk * h[s] + du * row[8 + s];
                y += h[s] * row[24 + s];
                dAk *= p;
            }
        } else {
            #pragma unroll
            for (int s = 0; s < 16; s++) {
                const float dA = __expf(dt * Av[s]);
                h[s] = dA * h[s] + du * row[8 + s];
                y += h[s] * row[24 + s];
            }
        }
        yp[(size_t)t * 256] = __float2bfloat16((y + Dpv * xcv) * sz);
    }
}

// ---------------- launch ----------------
extern "C" void kernel_launch(void* const* d_in, const int* in_sizes, int n_in,
                              void* d_out, int out_size)
{
    const float* x      = (const float*)d_in[0];
    const float* ng     = (const float*)d_in[1];
    const float* nb     = (const float*)d_in[2];
    const float* in_w   = (const float*)d_in[3];
    const float* conv_w = (const float*)d_in[4];
    const float* conv_b = (const float*)d_in[5];
    const float* xp_w   = (const float*)d_in[6];
    const float* dt_w   = (const float*)d_in[7];
    const float* dt_b   = (const float*)d_in[8];
    const float* A_log  = (const float*)d_in[9];
    const float* Dparam = (const float*)d_in[10];
    const float* out_w  = (const float*)d_in[11];
    const float* fw     = (const float*)d_in[12];
    const float* fb     = (const float*)d_in[13];
    const float* pw     = (const float*)d_in[14];
    const float* pb     = (const float*)d_in[15];
    float* out = (float*)d_out;

    // dynamic smem sizes: A[128][Kc+8] + B[2][64][40] (+ Cs[128][72] for MODE1)
    const int smem1 = 128 * 136 * 2 + 10240 + 128 * 72 * 2;  // 63488
    const int smem2 = 128 * 264 * 2 + 10240;                 // 77824
    const int smem3 = 128 * 392 * 2 + 10240;                 // 110592
    cudaFuncSetAttribute(bgemm_nl_kernel<1>, cudaFuncAttributeMaxDynamicSharedMemorySize, smem1);
    cudaFuncSetAttribute(bgemm_nl_kernel<2>, cudaFuncAttributeMaxDynamicSharedMemorySize, smem2);
    cudaFuncSetAttribute(bgemm_nl_kernel<3>, cudaFuncAttributeMaxDynamicSharedMemorySize, smem3);

    cvt_kernel<<<(3 * 512 * 128 + 255) / 256, 256>>>(in_w, xp_w, out_w, fw, pw);
    ln_kernel<<<VV / 32, 256>>>(x, ng, nb);
    bgemm_nl_kernel<1><<<dim3(VV / 128, 3), 256, smem1>>>(nullptr, conv_w, conv_b);  // in_proj+conv+silu
    bgemm_kernel<0><<<dim3(1, VV / 128, 3), 256>>>(nullptr, nullptr, nullptr);       // x_proj
    scan_kernel<<<dim3(NSEQ, 3), 256>>>(dt_w, dt_b, A_log, Dparam);
    bgemm_nl_kernel<2><<<dim3(VV / 128, 3), 256, smem2>>>(nullptr, nullptr, nullptr); // out_proj
    bgemm_nl_kernel<3><<<dim3(VV / 128, 1), 256, smem3>>>(fb, nullptr, nullptr);      // fusion+gelu
    bgemm_kernel<4><<<dim3(VV / 64, 1, 1), 256>>>(pb, x, out);                        // proj+residual
}

// round 6
// speedup vs baseline: 1.0953x; 1.0953x over previous
#include <cuda_runtime.h>
#include <cuda_bf16.h>
#include <cstdint>
#include <math.h>

typedef unsigned int u32;

#define VV    32768
#define NSEQ  1024
#define LSEQ  32
#define CD    128
#define DIc   256

typedef __nv_bfloat16 bf16;

// ---------------- scratch (device globals: allocation-free) ----------------
__device__ __align__(16) bf16  g_xn  [(size_t)VV * CD];       // normalized x, [vox][C]
__device__ __align__(16) bf16  g_z   [3ull * VV * DIc];       // silu(z),     [r][n][t][256]
__device__ __align__(16) bf16  g_xc  [3ull * VV * DIc];       // conv+silu,   [r][n][t][256]
__device__ __align__(16) bf16  g_ymid[3ull * VV * DIc];       // scan out,    [r][n][t][256]
__device__ __align__(16) bf16  g_yb  [(size_t)VV * 384];      // cat [vox][3*128]
__device__ __align__(16) bf16  g_f   [(size_t)VV * CD];       // gelu(fusion) [vox][128]

// bf16 weights
__device__ __align__(16) bf16 g_w_in [3 * 512 * 128];
__device__ __align__(16) bf16 g_w_xp [3 * 40 * 256];
__device__ __align__(16) bf16 g_w_out[3 * 128 * 256];
__device__ __align__(16) bf16 g_w_f  [128 * 384];
__device__ __align__(16) bf16 g_w_p  [128 * 128];

// branch (r) sequence (n,t) -> voxel index (d*1024 + h*32 + w)
__device__ __forceinline__ int vox_of(int r, int m) {
    int n = m >> 5, t = m & 31;
    if (r == 0) return (t << 10) + n;                              // axial
    if (r == 1) return ((n >> 5) << 10) + (t << 5) + (n & 31);     // coronal
    return (n << 5) + t;                                           // sagittal
}

// ---------------- weight convert fp32 -> bf16 ----------------
__global__ __launch_bounds__(256) void cvt_kernel(
    const float* __restrict__ in_w, const float* __restrict__ xp_w,
    const float* __restrict__ out_w, const float* __restrict__ fw,
    const float* __restrict__ pw)
{
    const int i = blockIdx.x * 256 + threadIdx.x;
    if (i < 3 * 512 * 128) g_w_in[i]  = __float2bfloat16(in_w[i]);
    if (i < 3 * 40 * 256)  g_w_xp[i]  = __float2bfloat16(xp_w[i]);
    if (i < 3 * 128 * 256) g_w_out[i] = __float2bfloat16(out_w[i]);
    if (i < 128 * 384)     g_w_f[i]   = __float2bfloat16(fw[i]);
    if (i < 128 * 128)     g_w_p[i]   = __float2bfloat16(pw[i]);
}

// ---------------- LayerNorm over channels, write bf16 [vox][C] ----------------
__global__ __launch_bounds__(256) void ln_kernel(
    const float* __restrict__ x, const float* __restrict__ g, const float* __restrict__ b)
{
    __shared__ float sm[128][33];
    __shared__ float smu[32], srs[32];
    const int v0 = blockIdx.x * 32;
    const int tid = threadIdx.x;

    #pragma unroll
    for (int it = 0; it < 16; it++) {
        int e = it * 256 + tid;
        int c = e >> 5, vi = e & 31;
        sm[c][vi] = x[(size_t)c * VV + v0 + vi];
    }
    __syncthreads();
    if (tid < 32) {
        float s = 0.f, s2 = 0.f;
        #pragma unroll 8
        for (int c = 0; c < 128; c++) { float v = sm[c][tid]; s += v; s2 += v * v; }
        float m = s * (1.f / 128.f);
        float var = s2 * (1.f / 128.f) - m * m;
        smu[tid] = m;
        srs[tid] = rsqrtf(var + 1e-5f);
    }
    __syncthreads();
    #pragma unroll
    for (int it = 0; it < 16; it++) {
        int e = it * 256 + tid;
        int c = e & 127, vi = e >> 7;
        float v = (sm[c][vi] - smu[vi]) * srs[vi] * g[c] + b[c];
        g_xn[(size_t)(v0 + vi) * 128 + c] = __float2bfloat16(v);
    }
}

// ---------------- tensor-core / async-copy helpers ----------------
__device__ __forceinline__ void ldsm4(u32* r, const void* p) {
    u32 addr = (u32)__cvta_generic_to_shared(p);
    asm volatile("ldmatrix.sync.aligned.m8n8.x4.shared.b16 {%0,%1,%2,%3}, [%4];"
        : "=r"(r[0]), "=r"(r[1]), "=r"(r[2]), "=r"(r[3]) : "r"(addr));
}
__device__ __forceinline__ void mma16816(float* c, const u32* a, u32 b0, u32 b1) {
    asm volatile("mma.sync.aligned.m16n8k16.row.col.f32.bf16.bf16.f32 "
        "{%0,%1,%2,%3}, {%4,%5,%6,%7}, {%8,%9}, {%0,%1,%2,%3};"
        : "+f"(c[0]), "+f"(c[1]), "+f"(c[2]), "+f"(c[3])
        : "r"(a[0]), "r"(a[1]), "r"(a[2]), "r"(a[3]), "r"(b0), "r"(b1));
}
__device__ __forceinline__ void cpa16(void* dst, const void* src, bool pred) {
    u32 d = (u32)__cvta_generic_to_shared(dst);
    int sz = pred ? 16 : 0;
    asm volatile("cp.async.ca.shared.global [%0], [%1], 16, %2;" :: "r"(d), "l"(src), "r"(sz));
}
__device__ __forceinline__ void cpa_commit() { asm volatile("cp.async.commit_group;"); }
template <int N> __device__ __forceinline__ void cpa_wait() {
    asm volatile("cp.async.wait_group %0;" :: "n"(N));
}
__device__ __forceinline__ float siluf(float s) { return s / (1.f + __expf(-s)); }

// ---------------- bf16 tensor-core GEMM (round-4 proven structure) ----------------
// MODE 1: in_proj  A=g_xn gathered,B=g_w_in[r](512x128)  -> epilogue conv+silu -> g_xc / silu -> g_z
// MODE 2: out_proj A=g_ymid[r],    B=g_w_out[r](128x256) -> scatter g_yb (bf16)
// MODE 3: fusion   A=g_yb (K=384), B=g_w_f(128x384), +bias, gelu -> g_f (bf16)
// MODE 4: proj     A=g_w_p,        B=g_f (N=VV), +bias +residual -> out (fp32)
template <int MODE>
__global__ __launch_bounds__(256) void bgemm_kernel(
    const float* __restrict__ bias, const float* __restrict__ resid, float* __restrict__ outp,
    const float* __restrict__ conv_w, const float* __restrict__ conv_b)
{
    constexpr int Kc = (MODE == 1) ? 128 : (MODE == 3) ? 384 : (MODE == 4) ? 128 : 256;
    constexpr int Nc = (MODE == 1) ? 512 : (MODE == 4) ? VV : 128;
    constexpr int NSTAGE = Kc / 32;

    __shared__ __align__(16) bf16 As[2][128][40];
    __shared__ __align__(16) bf16 Bs[2][64][40];

    const int r   = blockIdx.z;
    const int m0  = blockIdx.y * 128;
    const int j0  = blockIdx.x * 64;
    const int tid = threadIdx.x;
    const int lane = tid & 31, warp = tid >> 5;
    const int wm = (warp & 3) * 32, wn = (warp >> 2) * 32;

    const bf16* Abase = nullptr;
    const bf16* Bbase = nullptr;
    if (MODE == 1)      { Abase = g_xn;                          Bbase = g_w_in  + (size_t)r * 512 * 128; }
    else if (MODE == 2) { Abase = g_ymid + (size_t)r * VV * 256; Bbase = g_w_out + (size_t)r * 128 * 256; }
    else if (MODE == 3) { Abase = g_yb;                          Bbase = g_w_f; }
    else                { Abase = g_w_p;                         Bbase = g_f; }

    const int lrow = tid >> 2;
    const int lk8  = (tid & 3) << 3;

    const bf16 *arow0, *arow1;
    if (MODE == 1) {
        arow0 = g_xn + (size_t)vox_of(r, m0 + lrow) * 128;
        arow1 = g_xn + (size_t)vox_of(r, m0 + lrow + 64) * 128;
    } else {
        arow0 = Abase + (size_t)(m0 + lrow) * Kc;
        arow1 = Abase + (size_t)(m0 + lrow + 64) * Kc;
    }
    const int bj = j0 + lrow;
    const bf16* brow = Bbase + (size_t)bj * Kc;
    const bool bvalid = (Nc % 64 == 0) || (bj < Nc);

    float acc[2][4][4];
    #pragma unroll
    for (int f = 0; f < 2; f++)
        #pragma unroll
        for (int n = 0; n < 4; n++)
            #pragma unroll
            for (int i = 0; i < 4; i++) acc[f][n][i] = 0.f;

    const int srow = lane & 15;
    const int scol = (lane >> 4) << 3;

    cpa16(&As[0][lrow     ][lk8], arow0 + lk8, true);
    cpa16(&As[0][lrow + 64][lk8], arow1 + lk8, true);
    cpa16(&Bs[0][lrow     ][lk8], brow  + lk8, bvalid);
    cpa_commit();

    int sb = 0;
    #pragma unroll
    for (int st = 0; st < NSTAGE; st++) {
        const int kn = (st + 1) * 32;
        if (kn < Kc) {
            cpa16(&As[sb ^ 1][lrow     ][lk8], arow0 + kn + lk8, true);
            cpa16(&As[sb ^ 1][lrow + 64][lk8], arow1 + kn + lk8, true);
            cpa16(&Bs[sb ^ 1][lrow     ][lk8], brow  + kn + lk8, bvalid);
        }
        cpa_commit();
        cpa_wait<1>();
        __syncthreads();
        #pragma unroll
        for (int kk = 0; kk < 32; kk += 16) {
            u32 a[2][4], b[2][4];
            ldsm4(a[0], &As[sb][wm +      srow][kk + scol]);
            ldsm4(a[1], &As[sb][wm + 16 + srow][kk + scol]);
            ldsm4(b[0], &Bs[sb][wn +      srow][kk + scol]);
            ldsm4(b[1], &Bs[sb][wn + 16 + srow][kk + scol]);
            #pragma unroll
            for (int f = 0; f < 2; f++)
                #pragma unroll
                for (int n = 0; n < 4; n++)
                    mma16816(acc[f][n], a[f], b[n >> 1][n & 1], b[n >> 1][(n & 1) + 2]);
        }
        __syncthreads();
        sb ^= 1;
    }

    // ---- epilogue ----
    const int grp = lane >> 2, tg = lane & 3;

    if (MODE == 1) {
        __shared__ bf16 Cs[128][72];
        if (j0 < 256) {
            #pragma unroll
            for (int f = 0; f < 2; f++)
                #pragma unroll
                for (int half = 0; half < 2; half++) {
                    const int mm = wm + f * 16 + grp + half * 8;
                    #pragma unroll
                    for (int n = 0; n < 4; n++) {
                        const int jj = wn + n * 8 + tg * 2;
                        Cs[mm][jj]     = __float2bfloat16(acc[f][n][half * 2 + 0]);
                        Cs[mm][jj + 1] = __float2bfloat16(acc[f][n][half * 2 + 1]);
                    }
                }
            __syncthreads();
            const int c = tid & 63, sq = tid >> 6;
            const int gdi = j0 + c;
            const int wb = (r * 256 + gdi) * 4;
            const float w0 = conv_w[wb], w1 = conv_w[wb + 1], w2 = conv_w[wb + 2], w3 = conv_w[wb + 3];
            const float cb = conv_b[r * 256 + gdi];
            float x0 = 0.f, x1 = 0.f, x2 = 0.f;
            bf16* dst = g_xc + ((size_t)r * VV + m0 + sq * 32) * 256 + gdi;
            #pragma unroll
            for (int t = 0; t < 32; t++) {
                const float xv = __bfloat162float(Cs[sq * 32 + t][c]);
                const float s = x0 * w0 + x1 * w1 + x2 * w2 + xv * w3 + cb;
                dst[(size_t)t * 256] = __float2bfloat16(siluf(s));
                x0 = x1; x1 = x2; x2 = xv;
            }
        } else {
            #pragma unroll
            for (int f = 0; f < 2; f++)
                #pragma unroll
                for (int half = 0; half < 2; half++) {
                    const int m = m0 + wm + f * 16 + grp + half * 8;
                    #pragma unroll
                    for (int n = 0; n < 4; n++) {
                        const int j = j0 - 256 + wn + n * 8 + tg * 2;
                        __nv_bfloat162 v;
                        v.x = __float2bfloat16(siluf(acc[f][n][half * 2 + 0]));
                        v.y = __float2bfloat16(siluf(acc[f][n][half * 2 + 1]));
                        *(__nv_bfloat162*)&g_z[((size_t)r * VV + m) * 256 + j] = v;
                    }
                }
        }
        return;
    }

    #pragma unroll
    for (int f = 0; f < 2; f++) {
        #pragma unroll
        for (int half = 0; half < 2; half++) {
            const int m = m0 + wm + f * 16 + grp + half * 8;
            int vox = 0;
            if (MODE == 2) vox = vox_of(r, m);
            #pragma unroll
            for (int n = 0; n < 4; n++) {
                const int j = j0 + wn + n * 8 + tg * 2;
                const float c0 = acc[f][n][half * 2 + 0];
                const float c1 = acc[f][n][half * 2 + 1];
                if (MODE == 2) {
                    __nv_bfloat162 v; v.x = __float2bfloat16(c0); v.y = __float2bfloat16(c1);
                    *(__nv_bfloat162*)&g_yb[(size_t)vox * 384 + r * 128 + j] = v;
                } else if (MODE == 3) {
                    float u0 = c0 + bias[j], u1 = c1 + bias[j + 1];
                    float gl0 = 0.5f * u0 * (1.f + erff(u0 * 0.70710678118654752f));
                    float gl1 = 0.5f * u1 * (1.f + erff(u1 * 0.70710678118654752f));
                    __nv_bfloat162 v; v.x = __float2bfloat16(gl0); v.y = __float2bfloat16(gl1);
                    *(__nv_bfloat162*)&g_f[(size_t)m * 128 + j] = v;
                } else {
                    float2 rd = *(const float2*)&resid[(size_t)m * VV + j];
                    *(float2*)&outp[(size_t)m * VV + j] =
                        make_float2(c0 + bias[m] + rd.x, c1 + bias[m] + rd.y);
                }
            }
        }
    }
}

// ============ fused x_proj GEMM + dt + selective scan + gate ============
// Block: 128 rows (= 4 complete sequences) of branch r.
// Phase 1: dbl[128][40] = xc @ x_proj_w^T  (tensor cores, smem-resident result)
// Phase 2: per-channel scan over the 4 sequences, reading dbl from smem.
__global__ __launch_bounds__(256) void xps_kernel(
    const float* __restrict__ dt_w, const float* __restrict__ dt_b,
    const float* __restrict__ A_log, const float* __restrict__ Dparam)
{
    extern __shared__ __align__(16) char dyn[];
    bf16*  As = (bf16*)dyn;                    // [2][128][40]
    bf16*  Bs = (bf16*)(dyn + 20480);          // [2][64][40]
    float* Ds = (float*)(dyn + 30720);         // [128][44]

    const int r   = blockIdx.y;
    const int m0  = blockIdx.x * 128;
    const int tid = threadIdx.x;
    const int lane = tid & 31, warp = tid >> 5;
    const int wm = (warp & 3) * 32, wn = (warp >> 2) * 32;
    const int lrow = tid >> 2;
    const int lk8  = (tid & 3) << 3;
    const int srow = lane & 15;
    const int scol = (lane >> 4) << 3;

    const bf16* Abase = g_xc   + (size_t)r * VV * 256;
    const bf16* Bbase = g_w_xp + (size_t)r * 40 * 256;
    const bf16* arow0 = Abase + (size_t)(m0 + lrow) * 256;
    const bf16* arow1 = Abase + (size_t)(m0 + lrow + 64) * 256;
    const bf16* brow  = Bbase + (size_t)lrow * 256;
    const bool bvalid = (lrow < 40);

    float acc[2][4][4];
    #pragma unroll
    for (int f = 0; f < 2; f++)
        #pragma unroll
        for (int n = 0; n < 4; n++)
            #pragma unroll
            for (int i = 0; i < 4; i++) acc[f][n][i] = 0.f;

    cpa16(As + 0 * 5120 + lrow * 40 + lk8,        arow0 + lk8, true);
    cpa16(As + 0 * 5120 + (lrow + 64) * 40 + lk8, arow1 + lk8, true);
    cpa16(Bs + 0 * 2560 + lrow * 40 + lk8,        brow  + lk8, bvalid);
    cpa_commit();

    int sb = 0;
    #pragma unroll
    for (int st = 0; st < 8; st++) {
        const int kn = (st + 1) * 32;
        if (kn < 256) {
            cpa16(As + (sb ^ 1) * 5120 + lrow * 40 + lk8,        arow0 + kn + lk8, true);
            cpa16(As + (sb ^ 1) * 5120 + (lrow + 64) * 40 + lk8, arow1 + kn + lk8, true);
            cpa16(Bs + (sb ^ 1) * 2560 + lrow * 40 + lk8,        brow  + kn + lk8, bvalid);
        }
        cpa_commit();
        cpa_wait<1>();
        __syncthreads();
        #pragma unroll
        for (int kk = 0; kk < 32; kk += 16) {
            u32 a[2][4], b[2][4];
            ldsm4(a[0], As + sb * 5120 + (wm +      srow) * 40 + kk + scol);
            ldsm4(a[1], As + sb * 5120 + (wm + 16 + srow) * 40 + kk + scol);
            ldsm4(b[0], Bs + sb * 2560 + (wn +      srow) * 40 + kk + scol);
            ldsm4(b[1], Bs + sb * 2560 + (wn + 16 + srow) * 40 + kk + scol);
            #pragma unroll
            for (int f = 0; f < 2; f++)
                #pragma unroll
                for (int n = 0; n < 4; n++)
                    mma16816(acc[f][n], a[f], b[n >> 1][n & 1], b[n >> 1][(n & 1) + 2]);
        }
        __syncthreads();
        sb ^= 1;
    }

    // stage dbl into smem
    const int grp = lane >> 2, tg = lane & 3;
    #pragma unroll
    for (int f = 0; f < 2; f++)
        #pragma unroll
        for (int half = 0; half < 2; half++) {
            const int m = wm + f * 16 + grp + half * 8;
            #pragma unroll
            for (int n = 0; n < 4; n++) {
                const int j = wn + n * 8 + tg * 2;
                if (j < 40)
                    *(float2*)&Ds[m * 44 + j] =
                        make_float2(acc[f][n][half * 2 + 0], acc[f][n][half * 2 + 1]);
            }
        }
    __syncthreads();

    // ---- scan over 4 sequences, 256 threads = 256 DI channels ----
    const int di = tid;
    float dtw[8];
    #pragma unroll
    for (int k = 0; k < 8; k++) dtw[k] = dt_w[(r * 256 + di) * 8 + k];
    const float dtb = dt_b[r * 256 + di];
    const float Dpv = Dparam[r * 256 + di];

    float Av[16];
    #pragma unroll
    for (int s = 0; s < 16; s++) Av[s] = -__expf(A_log[(r * 256 + di) * 16 + s]);
    bool ap = true;
    #pragma unroll
    for (int s = 1; s < 16; s++)
        ap = ap && (fabsf(Av[s] - (float)(s + 1) * Av[0]) <= 1e-4f * fabsf(Av[s]) + 1e-6f);

    const bf16* xcp = g_xc   + ((size_t)r * VV + m0) * 256 + di;
    const bf16* zp  = g_z    + ((size_t)r * VV + m0) * 256 + di;
    bf16*       yp  = g_ymid + ((size_t)r * VV + m0) * 256 + di;

    for (int sq = 0; sq < 4; sq++) {
        float h[16];
        #pragma unroll
        for (int s = 0; s < 16; s++) h[s] = 0.f;

        for (int t = 0; t < LSEQ; t++) {
            const int row = sq * 32 + t;
            const float* dr = Ds + row * 44;
            float xl = dtb;
            #pragma unroll
            for (int k = 0; k < 8; k++) xl += dr[k] * dtw[k];
            const float dt = (xl > 15.f) ? xl : log1pf(__expf(xl));

            const float xcv = __bfloat162float(xcp[(size_t)row * 256]);
            const float sz  = __bfloat162float(zp [(size_t)row * 256]);
            const float du  = dt * xcv;
            float y = 0.f;

            if (ap) {
                const float p = __expf(dt * Av[0]);
                float dAk = p;
                #pragma unroll
                for (int s = 0; s < 16; s++) {
                    h[s] = dAk * h[s] + du * dr[8 + s];
                    y += h[s] * dr[24 + s];
                    dAk *= p;
                }
            } else {
                #pragma unroll
                for (int s = 0; s < 16; s++) {
                    const float dA = __expf(dt * Av[s]);
                    h[s] = dA * h[s] + du * dr[8 + s];
                    y += h[s] * dr[24 + s];
                }
            }
            yp[(size_t)row * 256] = __float2bfloat16((y + Dpv * xcv) * sz);
        }
    }
}

// ---------------- launch ----------------
extern "C" void kernel_launch(void* const* d_in, const int* in_sizes, int n_in,
                              void* d_out, int out_size)
{
    const float* x      = (const float*)d_in[0];
    const float* ng     = (const float*)d_in[1];
    const float* nb     = (const float*)d_in[2];
    const float* in_w   = (const float*)d_in[3];
    const float* conv_w = (const float*)d_in[4];
    const float* conv_b = (const float*)d_in[5];
    const float* xp_w   = (const float*)d_in[6];
    const float* dt_w   = (const float*)d_in[7];
    const float* dt_b   = (const float*)d_in[8];
    const float* A_log  = (const float*)d_in[9];
    const float* Dparam = (const float*)d_in[10];
    const float* out_w  = (const float*)d_in[11];
    const float* fw     = (const float*)d_in[12];
    const float* fb     = (const float*)d_in[13];
    const float* pw     = (const float*)d_in[14];
    const float* pb     = (const float*)d_in[15];
    float* out = (float*)d_out;

    const int smem_xps = 20480 + 10240 + 128 * 44 * 4;  // 53248
    cudaFuncSetAttribute(xps_kernel, cudaFuncAttributeMaxDynamicSharedMemorySize, smem_xps);

    cvt_kernel<<<(3 * 512 * 128 + 255) / 256, 256>>>(in_w, xp_w, out_w, fw, pw);
    ln_kernel<<<VV / 32, 256>>>(x, ng, nb);
    bgemm_kernel<1><<<dim3(8, VV / 128, 3), 256>>>(nullptr, nullptr, nullptr, conv_w, conv_b); // in_proj+conv+silu
    xps_kernel<<<dim3(VV / 128, 3), 256, smem_xps>>>(dt_w, dt_b, A_log, Dparam);               // x_proj+scan
    bgemm_kernel<2><<<dim3(2, VV / 128, 3), 256>>>(nullptr, nullptr, nullptr, nullptr, nullptr); // out_proj
    bgemm_kernel<3><<<dim3(2, VV / 128, 1), 256>>>(fb, nullptr, nullptr, nullptr, nullptr);      // fusion+gelu
    bgemm_kernel<4><<<dim3(VV / 64, 1, 1), 256>>>(pb, x, out, nullptr, nullptr);                 // proj+residual
}

// round 7
// speedup vs baseline: 1.1935x; 1.0896x over previous
#include <cuda_runtime.h>
#include <cuda_bf16.h>
#include <cstdint>
#include <math.h>

typedef unsigned int u32;

#define VV    32768
#define NSEQ  1024
#define LSEQ  32
#define CD    128
#define DIc   256

typedef __nv_bfloat16 bf16;

// ---------------- scratch (device globals: allocation-free) ----------------
__device__ __align__(16) bf16  g_xn  [(size_t)VV * CD];       // normalized x, [vox][C]
__device__ __align__(16) bf16  g_z   [3ull * VV * DIc];       // silu(z),     [r][n][t][256]
__device__ __align__(16) bf16  g_xc  [3ull * VV * DIc];       // conv+silu,   [r][n][t][256]
__device__ __align__(16) float g_dbl [3ull * VV * 40];        // x_proj out,  [r][n][t][40]
__device__ __align__(16) bf16  g_ymid[3ull * VV * DIc];       // scan out,    [r][n][t][256]
__device__ __align__(16) bf16  g_yb  [(size_t)VV * 384];      // cat [vox][3*128]
__device__ __align__(16) bf16  g_f   [(size_t)VV * CD];       // gelu(fusion) [vox][128]

// bf16 weights
__device__ __align__(16) bf16 g_w_in [3 * 512 * 128];
__device__ __align__(16) bf16 g_w_xp [3 * 40 * 256];
__device__ __align__(16) bf16 g_w_out[3 * 128 * 256];
__device__ __align__(16) bf16 g_w_f  [128 * 384];
__device__ __align__(16) bf16 g_w_p  [128 * 128];

// branch (r) sequence (n,t) -> voxel index (d*1024 + h*32 + w)
__device__ __forceinline__ int vox_of(int r, int m) {
    int n = m >> 5, t = m & 31;
    if (r == 0) return (t << 10) + n;                              // axial
    if (r == 1) return ((n >> 5) << 10) + (t << 5) + (n & 31);     // coronal
    return (n << 5) + t;                                           // sagittal
}

// ---------------- weight convert fp32 -> bf16 ----------------
__global__ __launch_bounds__(256) void cvt_kernel(
    const float* __restrict__ in_w, const float* __restrict__ xp_w,
    const float* __restrict__ out_w, const float* __restrict__ fw,
    const float* __restrict__ pw)
{
    const int i = blockIdx.x * 256 + threadIdx.x;
    if (i < 3 * 512 * 128) g_w_in[i]  = __float2bfloat16(in_w[i]);
    if (i < 3 * 40 * 256)  g_w_xp[i]  = __float2bfloat16(xp_w[i]);
    if (i < 3 * 128 * 256) g_w_out[i] = __float2bfloat16(out_w[i]);
    if (i < 128 * 384)     g_w_f[i]   = __float2bfloat16(fw[i]);
    if (i < 128 * 128)     g_w_p[i]   = __float2bfloat16(pw[i]);
}

// ---------------- LayerNorm over channels, write bf16 [vox][C] ----------------
__global__ __launch_bounds__(256) void ln_kernel(
    const float* __restrict__ x, const float* __restrict__ g, const float* __restrict__ b)
{
    __shared__ float sm[128][33];
    __shared__ float smu[32], srs[32];
    const int v0 = blockIdx.x * 32;
    const int tid = threadIdx.x;

    #pragma unroll
    for (int it = 0; it < 16; it++) {
        int e = it * 256 + tid;
        int c = e >> 5, vi = e & 31;
        sm[c][vi] = x[(size_t)c * VV + v0 + vi];
    }
    __syncthreads();
    if (tid < 32) {
        float s = 0.f, s2 = 0.f;
        #pragma unroll 8
        for (int c = 0; c < 128; c++) { float v = sm[c][tid]; s += v; s2 += v * v; }
        float m = s * (1.f / 128.f);
        float var = s2 * (1.f / 128.f) - m * m;
        smu[tid] = m;
        srs[tid] = rsqrtf(var + 1e-5f);
    }
    __syncthreads();
    #pragma unroll
    for (int it = 0; it < 16; it++) {
        int e = it * 256 + tid;
        int c = e & 127, vi = e >> 7;
        float v = (sm[c][vi] - smu[vi]) * srs[vi] * g[c] + b[c];
        g_xn[(size_t)(v0 + vi) * 128 + c] = __float2bfloat16(v);
    }
}

// ---------------- tensor-core / async-copy helpers ----------------
__device__ __forceinline__ void ldsm4(u32* r, const void* p) {
    u32 addr = (u32)__cvta_generic_to_shared(p);
    asm volatile("ldmatrix.sync.aligned.m8n8.x4.shared.b16 {%0,%1,%2,%3}, [%4];"
        : "=r"(r[0]), "=r"(r[1]), "=r"(r[2]), "=r"(r[3]) : "r"(addr));
}
__device__ __forceinline__ void mma16816(float* c, const u32* a, u32 b0, u32 b1) {
    asm volatile("mma.sync.aligned.m16n8k16.row.col.f32.bf16.bf16.f32 "
        "{%0,%1,%2,%3}, {%4,%5,%6,%7}, {%8,%9}, {%0,%1,%2,%3};"
        : "+f"(c[0]), "+f"(c[1]), "+f"(c[2]), "+f"(c[3])
        : "r"(a[0]), "r"(a[1]), "r"(a[2]), "r"(a[3]), "r"(b0), "r"(b1));
}
__device__ __forceinline__ void cpa16(void* dst, const void* src, bool pred) {
    u32 d = (u32)__cvta_generic_to_shared(dst);
    int sz = pred ? 16 : 0;
    asm volatile("cp.async.ca.shared.global [%0], [%1], 16, %2;" :: "r"(d), "l"(src), "r"(sz));
}
__device__ __forceinline__ void cpa_commit() { asm volatile("cp.async.commit_group;"); }
template <int N> __device__ __forceinline__ void cpa_wait() {
    asm volatile("cp.async.wait_group %0;" :: "n"(N));
}
__device__ __forceinline__ float siluf(float s) { return s / (1.f + __expf(-s)); }

// ---------------- bf16 tensor-core GEMM (round-4 proven structure) ----------------
// MODE 0: x_proj   A=g_xc[r],      B=g_w_xp[r](40x256)   -> g_dbl (fp32)
// MODE 1: in_proj  A=g_xn gathered,B=g_w_in[r](512x128)  -> epilogue conv+silu -> g_xc / silu -> g_z
// MODE 2: out_proj A=g_ymid[r],    B=g_w_out[r](128x256) -> scatter g_yb (bf16)
// MODE 3: fusion   A=g_yb (K=384), B=g_w_f(128x384), +bias, gelu -> g_f (bf16)
// MODE 4: proj     A=g_w_p,        B=g_f (N=VV), +bias +residual -> out (fp32)
template <int MODE>
__global__ __launch_bounds__(256) void bgemm_kernel(
    const float* __restrict__ bias, const float* __restrict__ resid, float* __restrict__ outp,
    const float* __restrict__ conv_w, const float* __restrict__ conv_b)
{
    constexpr int Kc = (MODE == 1) ? 128 : (MODE == 3) ? 384 : (MODE == 4) ? 128 : 256;
    constexpr int Nc = (MODE == 1) ? 512 : (MODE == 0) ? 40 : (MODE == 4) ? VV : 128;
    constexpr int NSTAGE = Kc / 32;

    __shared__ __align__(16) bf16 As[2][128][40];
    __shared__ __align__(16) bf16 Bs[2][64][40];

    const int r   = blockIdx.z;
    const int m0  = blockIdx.y * 128;
    const int j0  = blockIdx.x * 64;
    const int tid = threadIdx.x;
    const int lane = tid & 31, warp = tid >> 5;
    const int wm = (warp & 3) * 32, wn = (warp >> 2) * 32;

    const bf16* Abase = nullptr;
    const bf16* Bbase = nullptr;
    if (MODE == 0)      { Abase = g_xc   + (size_t)r * VV * 256; Bbase = g_w_xp  + (size_t)r * 40 * 256; }
    else if (MODE == 1) { Abase = g_xn;                          Bbase = g_w_in  + (size_t)r * 512 * 128; }
    else if (MODE == 2) { Abase = g_ymid + (size_t)r * VV * 256; Bbase = g_w_out + (size_t)r * 128 * 256; }
    else if (MODE == 3) { Abase = g_yb;                          Bbase = g_w_f; }
    else                { Abase = g_w_p;                         Bbase = g_f; }

    const int lrow = tid >> 2;
    const int lk8  = (tid & 3) << 3;

    const bf16 *arow0, *arow1;
    if (MODE == 1) {
        arow0 = g_xn + (size_t)vox_of(r, m0 + lrow) * 128;
        arow1 = g_xn + (size_t)vox_of(r, m0 + lrow + 64) * 128;
    } else {
        arow0 = Abase + (size_t)(m0 + lrow) * Kc;
        arow1 = Abase + (size_t)(m0 + lrow + 64) * Kc;
    }
    const int bj = j0 + lrow;
    const bf16* brow = Bbase + (size_t)bj * Kc;
    const bool bvalid = (Nc % 64 == 0) || (bj < Nc);

    float acc[2][4][4];
    #pragma unroll
    for (int f = 0; f < 2; f++)
        #pragma unroll
        for (int n = 0; n < 4; n++)
            #pragma unroll
            for (int i = 0; i < 4; i++) acc[f][n][i] = 0.f;

    const int srow = lane & 15;
    const int scol = (lane >> 4) << 3;

    cpa16(&As[0][lrow     ][lk8], arow0 + lk8, true);
    cpa16(&As[0][lrow + 64][lk8], arow1 + lk8, true);
    cpa16(&Bs[0][lrow     ][lk8], brow  + lk8, bvalid);
    cpa_commit();

    int sb = 0;
    #pragma unroll
    for (int st = 0; st < NSTAGE; st++) {
        const int kn = (st + 1) * 32;
        if (kn < Kc) {
            cpa16(&As[sb ^ 1][lrow     ][lk8], arow0 + kn + lk8, true);
            cpa16(&As[sb ^ 1][lrow + 64][lk8], arow1 + kn + lk8, true);
            cpa16(&Bs[sb ^ 1][lrow     ][lk8], brow  + kn + lk8, bvalid);
        }
        cpa_commit();
        cpa_wait<1>();
        __syncthreads();
        #pragma unroll
        for (int kk = 0; kk < 32; kk += 16) {
            u32 a[2][4], b[2][4];
            ldsm4(a[0], &As[sb][wm +      srow][kk + scol]);
            ldsm4(a[1], &As[sb][wm + 16 + srow][kk + scol]);
            ldsm4(b[0], &Bs[sb][wn +      srow][kk + scol]);
            ldsm4(b[1], &Bs[sb][wn + 16 + srow][kk + scol]);
            #pragma unroll
            for (int f = 0; f < 2; f++)
                #pragma unroll
                for (int n = 0; n < 4; n++)
                    mma16816(acc[f][n], a[f], b[n >> 1][n & 1], b[n >> 1][(n & 1) + 2]);
        }
        __syncthreads();
        sb ^= 1;
    }

    // ---- epilogue ----
    const int grp = lane >> 2, tg = lane & 3;

    if (MODE == 1) {
        __shared__ bf16 Cs[128][72];
        if (j0 < 256) {
            #pragma unroll
            for (int f = 0; f < 2; f++)
                #pragma unroll
                for (int half = 0; half < 2; half++) {
                    const int mm = wm + f * 16 + grp + half * 8;
                    #pragma unroll
                    for (int n = 0; n < 4; n++) {
                        const int jj = wn + n * 8 + tg * 2;
                        Cs[mm][jj]     = __float2bfloat16(acc[f][n][half * 2 + 0]);
                        Cs[mm][jj + 1] = __float2bfloat16(acc[f][n][half * 2 + 1]);
                    }
                }
            __syncthreads();
            const int c = tid & 63, sq = tid >> 6;
            const int gdi = j0 + c;
            const int wb = (r * 256 + gdi) * 4;
            const float w0 = conv_w[wb], w1 = conv_w[wb + 1], w2 = conv_w[wb + 2], w3 = conv_w[wb + 3];
            const float cb = conv_b[r * 256 + gdi];
            float x0 = 0.f, x1 = 0.f, x2 = 0.f;
            bf16* dst = g_xc + ((size_t)r * VV + m0 + sq * 32) * 256 + gdi;
            #pragma unroll
            for (int t = 0; t < 32; t++) {
                const float xv = __bfloat162float(Cs[sq * 32 + t][c]);
                const float s = x0 * w0 + x1 * w1 + x2 * w2 + xv * w3 + cb;
                dst[(size_t)t * 256] = __float2bfloat16(siluf(s));
                x0 = x1; x1 = x2; x2 = xv;
            }
        } else {
            #pragma unroll
            for (int f = 0; f < 2; f++)
                #pragma unroll
                for (int half = 0; half < 2; half++) {
                    const int m = m0 + wm + f * 16 + grp + half * 8;
                    #pragma unroll
                    for (int n = 0; n < 4; n++) {
                        const int j = j0 - 256 + wn + n * 8 + tg * 2;
                        __nv_bfloat162 v;
                        v.x = __float2bfloat16(siluf(acc[f][n][half * 2 + 0]));
                        v.y = __float2bfloat16(siluf(acc[f][n][half * 2 + 1]));
                        *(__nv_bfloat162*)&g_z[((size_t)r * VV + m) * 256 + j] = v;
                    }
                }
        }
        return;
    }

    #pragma unroll
    for (int f = 0; f < 2; f++) {
        #pragma unroll
        for (int half = 0; half < 2; half++) {
            const int m = m0 + wm + f * 16 + grp + half * 8;
            int vox = 0;
            if (MODE == 2) vox = vox_of(r, m);
            #pragma unroll
            for (int n = 0; n < 4; n++) {
                const int j = j0 + wn + n * 8 + tg * 2;
                const float c0 = acc[f][n][half * 2 + 0];
                const float c1 = acc[f][n][half * 2 + 1];
                if (MODE == 0) {
                    if (j < 40)
                        *(float2*)&g_dbl[(size_t)r * VV * 40 + (size_t)m * 40 + j] = make_float2(c0, c1);
                } else if (MODE == 2) {
                    __nv_bfloat162 v; v.x = __float2bfloat16(c0); v.y = __float2bfloat16(c1);
                    *(__nv_bfloat162*)&g_yb[(size_t)vox * 384 + r * 128 + j] = v;
                } else if (MODE == 3) {
                    float u0 = c0 + bias[j], u1 = c1 + bias[j + 1];
                    float gl0 = 0.5f * u0 * (1.f + erff(u0 * 0.70710678118654752f));
                    float gl1 = 0.5f * u1 * (1.f + erff(u1 * 0.70710678118654752f));
                    __nv_bfloat162 v; v.x = __float2bfloat16(gl0); v.y = __float2bfloat16(gl1);
                    *(__nv_bfloat162*)&g_f[(size_t)m * 128 + j] = v;
                } else {
                    float2 rd = *(const float2*)&resid[(size_t)m * VV + j];
                    *(float2*)&outp[(size_t)m * VV + j] =
                        make_float2(c0 + bias[m] + rd.x, c1 + bias[m] + rd.y);
                }
            }
        }
    }
}

// ---------------- optimized dt + selective scan + gate ----------------
// One block per (sequence, branch): 256 threads = 256 DI channels, 32 serial steps.
// float4 smem reads, 4-group power ladder (no serial dAk chain), tree y-reduce.
__global__ __launch_bounds__(256) void scan_kernel(
    const float* __restrict__ dt_w, const float* __restrict__ dt_b,
    const float* __restrict__ A_log, const float* __restrict__ Dparam)
{
    __shared__ __align__(16) float sm[LSEQ * 40];
    const int r = blockIdx.y, n = blockIdx.x, di = threadIdx.x;

    const float* dblp = g_dbl + (size_t)(r * NSEQ + n) * LSEQ * 40;
    #pragma unroll
    for (int e = di; e < LSEQ * 10; e += 256)
        ((float4*)sm)[e] = ((const float4*)dblp)[e];
    __syncthreads();

    float dtw[8];
    #pragma unroll
    for (int k = 0; k < 8; k++) dtw[k] = dt_w[(r * 256 + di) * 8 + k];
    const float dtb = dt_b[r * 256 + di];
    const float Dpv = Dparam[r * 256 + di];

    // AP check: A[s] == (s+1)*A[0] (fast path); fallback recomputes A per step.
    const float Av0 = -__expf(A_log[(r * 256 + di) * 16]);
    bool ap = true;
    #pragma unroll
    for (int s = 1; s < 16; s++) {
        const float As = -__expf(A_log[(r * 256 + di) * 16 + s]);
        ap = ap && (fabsf(As - (float)(s + 1) * Av0) <= 1e-4f * fabsf(As) + 1e-6f);
    }

    float h[16];
    #pragma unroll
    for (int s = 0; s < 16; s++) h[s] = 0.f;

    const bf16* xcp = g_xc   + ((size_t)(r * NSEQ + n) * LSEQ) * 256 + di;
    const bf16* zp  = g_z    + ((size_t)(r * NSEQ + n) * LSEQ) * 256 + di;
    bf16*       yp  = g_ymid + ((size_t)(r * NSEQ + n) * LSEQ) * 256 + di;

    if (ap) {
        #pragma unroll 4
        for (int t = 0; t < LSEQ; t++) {
            const float4* ds4 = (const float4*)(sm + t * 40);
            const float4 d0 = ds4[0], d1 = ds4[1];
            float xl = dtb;
            xl = fmaf(d0.x, dtw[0], xl); xl = fmaf(d0.y, dtw[1], xl);
            xl = fmaf(d0.z, dtw[2], xl); xl = fmaf(d0.w, dtw[3], xl);
            xl = fmaf(d1.x, dtw[4], xl); xl = fmaf(d1.y, dtw[5], xl);
            xl = fmaf(d1.z, dtw[6], xl); xl = fmaf(d1.w, dtw[7], xl);
            const float dt = (xl > 15.f) ? xl : __logf(1.f + __expf(xl));

            const float xcv = __bfloat162float(xcp[(size_t)t * 256]);
            const float sz  = __bfloat162float(zp [(size_t)t * 256]);
            const float du  = dt * xcv;

            const float4 B0 = ds4[2], B1 = ds4[3], B2 = ds4[4], B3 = ds4[5];
            const float4 C0 = ds4[6], C1 = ds4[7], C2 = ds4[8], C3 = ds4[9];

            const float p1 = __expf(dt * Av0);
            const float p2 = p1 * p1;
            const float p4 = p2 * p2;
            float pa = p1, pb = p2, pc = p2 * p1, pd = p4;

            h[0]  = fmaf(pa, h[0],  du * B0.x);
            h[1]  = fmaf(pb, h[1],  du * B0.y);
            h[2]  = fmaf(pc, h[2],  du * B0.z);
            h[3]  = fmaf(pd, h[3],  du * B0.w);
            pa *= p4; pb *= p4; pc *= p4; pd *= p4;
            h[4]  = fmaf(pa, h[4],  du * B1.x);
            h[5]  = fmaf(pb, h[5],  du * B1.y);
            h[6]  = fmaf(pc, h[6],  du * B1.z);
            h[7]  = fmaf(pd, h[7],  du * B1.w);
            pa *= p4; pb *= p4; pc *= p4; pd *= p4;
            h[8]  = fmaf(pa, h[8],  du * B2.x);
            h[9]  = fmaf(pb, h[9],  du * B2.y);
            h[10] = fmaf(pc, h[10], du * B2.z);
            h[11] = fmaf(pd, h[11], du * B2.w);
            pa *= p4; pb *= p4; pc *= p4; pd *= p4;
            h[12] = fmaf(pa, h[12], du * B3.x);
            h[13] = fmaf(pb, h[13], du * B3.y);
            h[14] = fmaf(pc, h[14], du * B3.z);
            h[15] = fmaf(pd, h[15], du * B3.w);

            float y0 = h[0] * C0.x;  y0 = fmaf(h[1],  C0.y, y0);
            y0 = fmaf(h[2],  C0.z, y0); y0 = fmaf(h[3],  C0.w, y0);
            float y1 = h[4] * C1.x;  y1 = fmaf(h[5],  C1.y, y1);
            y1 = fmaf(h[6],  C1.z, y1); y1 = fmaf(h[7],  C1.w, y1);
            float y2 = h[8] * C2.x;  y2 = fmaf(h[9],  C2.y, y2);
            y2 = fmaf(h[10], C2.z, y2); y2 = fmaf(h[11], C2.w, y2);
            float y3 = h[12] * C3.x; y3 = fmaf(h[13], C3.y, y3);
            y3 = fmaf(h[14], C3.z, y3); y3 = fmaf(h[15], C3.w, y3);
            const float y = (y0 + y1) + (y2 + y3);

            yp[(size_t)t * 256] = __float2bfloat16(fmaf(Dpv, xcv, y) * sz);
        }
    } else {
        // generic fallback: recompute A per step (correctness path only)
        for (int t = 0; t < LSEQ; t++) {
            const float* row = sm + t * 40;
            float xl = dtb;
            #pragma unroll
            for (int k = 0; k < 8; k++) xl = fmaf(row[k], dtw[k], xl);
            const float dt = (xl > 15.f) ? xl : log1pf(__expf(xl));
            const float xcv = __bfloat162float(xcp[(size_t)t * 256]);
            const float sz  = __bfloat162float(zp [(size_t)t * 256]);
            const float du  = dt * xcv;
            float y = 0.f;
            #pragma unroll
            for (int s = 0; s < 16; s++) {
                const float Avs = -__expf(A_log[(r * 256 + di) * 16 + s]);
                const float dA = __expf(dt * Avs);
                h[s] = fmaf(dA, h[s], du * row[8 + s]);
                y = fmaf(h[s], row[24 + s], y);
            }
            yp[(size_t)t * 256] = __float2bfloat16(fmaf(Dpv, xcv, y) * sz);
        }
    }
}

// ---------------- launch ----------------
extern "C" void kernel_launch(void* const* d_in, const int* in_sizes, int n_in,
                              void* d_out, int out_size)
{
    const float* x      = (const float*)d_in[0];
    const float* ng     = (const float*)d_in[1];
    const float* nb     = (const float*)d_in[2];
    const float* in_w   = (const float*)d_in[3];
    const float* conv_w = (const float*)d_in[4];
    const float* conv_b = (const float*)d_in[5];
    const float* xp_w   = (const float*)d_in[6];
    const float* dt_w   = (const float*)d_in[7];
    const float* dt_b   = (const float*)d_in[8];
    const float* A_log  = (const float*)d_in[9];
    const float* Dparam = (const float*)d_in[10];
    const float* out_w  = (const float*)d_in[11];
    const float* fw     = (const float*)d_in[12];
    const float* fb     = (const float*)d_in[13];
    const float* pw     = (const float*)d_in[14];
    const float* pb     = (const float*)d_in[15];
    float* out = (float*)d_out;

    cvt_kernel<<<(3 * 512 * 128 + 255) / 256, 256>>>(in_w, xp_w, out_w, fw, pw);
    ln_kernel<<<VV / 32, 256>>>(x, ng, nb);
    bgemm_kernel<1><<<dim3(8, VV / 128, 3), 256>>>(nullptr, nullptr, nullptr, conv_w, conv_b); // in_proj+conv+silu
    bgemm_kernel<0><<<dim3(1, VV / 128, 3), 256>>>(nullptr, nullptr, nullptr, nullptr, nullptr); // x_proj
    scan_kernel<<<dim3(NSEQ, 3), 256>>>(dt_w, dt_b, A_log, Dparam);
    bgemm_kernel<2><<<dim3(2, VV / 128, 3), 256>>>(nullptr, nullptr, nullptr, nullptr, nullptr); // out_proj
    bgemm_kernel<3><<<dim3(2, VV / 128, 1), 256>>>(fb, nullptr, nullptr, nullptr, nullptr);      // fusion+gelu
    bgemm_kernel<4><<<dim3(VV / 64, 1, 1), 256>>>(pb, x, out, nullptr, nullptr);                 // proj+residual
}